// round 9
// baseline (speedup 1.0000x reference)
#include <cuda_runtime.h>

#define B_TOT    8192
#define T_LEN    512
#define F_IN     24
#define H_DIM    12
#define CHUNK    8
#define EPB      16           // elements per warp: 8 quad-slots x 2 elements/thread
#define NTHREADS 32           // single-warp blocks
#define NCHUNK   (T_LEN / CHUNK)
#define XS_STRIDE 28          // padded floats per (tt, elem) row (conflict-free)
#define XS_BUF_FLOATS (CHUNK * EPB * XS_STRIDE)   // 3584
#define SMEM_BYTES (2 * XS_BUF_FLOATS * 4)        // 28672

typedef unsigned long long u64;

__device__ __forceinline__ unsigned smem_u32(const void* p) {
    return (unsigned)__cvta_generic_to_shared(p);
}
__device__ __forceinline__ void cp_async16(unsigned dst, const void* src) {
    asm volatile("cp.async.cg.shared.global [%0], [%1], 16;\n" :: "r"(dst), "l"(src));
}
__device__ __forceinline__ void cp_commit() {
    asm volatile("cp.async.commit_group;\n" ::: "memory");
}
template <int N> __device__ __forceinline__ void cp_wait() {
    asm volatile("cp.async.wait_group %0;\n" :: "n"(N) : "memory");
}

// ---- packed f32x2 helpers ----
__device__ __forceinline__ u64 pack2(float lo, float hi) {
    u64 d; asm("mov.b64 %0, {%1, %2};" : "=l"(d) : "f"(lo), "f"(hi)); return d;
}
__device__ __forceinline__ void unpack2(u64 d, float& lo, float& hi) {
    asm("mov.b64 {%0, %1}, %2;" : "=f"(lo), "=f"(hi) : "l"(d));
}
__device__ __forceinline__ u64 fma2(u64 a, u64 b, u64 c) {
    u64 d; asm("fma.rn.f32x2 %0, %1, %2, %3;" : "=l"(d) : "l"(a), "l"(b), "l"(c)); return d;
}
__device__ __forceinline__ u64 add2(u64 a, u64 b) {
    u64 d; asm("add.rn.f32x2 %0, %1, %2;" : "=l"(d) : "l"(a), "l"(b)); return d;
}
__device__ __forceinline__ float hadd2(u64 a) {
    float lo, hi; unpack2(a, lo, hi); return lo + hi;
}

// tanh(x) = 1 - 2*rcp(exp(2x)+1); 5 instrs, correct saturation at +/-inf.
__device__ __forceinline__ float tanh_fast(float x) {
    float e;
    asm("ex2.approx.f32 %0, %1;" : "=f"(e) : "f"(x * 2.885390082f));
    float r;
    asm("rcp.approx.f32 %0, %1;" : "=f"(r) : "f"(e + 1.0f));
    return fmaf(-2.0f, r, 1.0f);
}

__global__ void __launch_bounds__(NTHREADS) rnn_fused_kernel(
    const float* __restrict__ x,
    const float* __restrict__ W_ih, const float* __restrict__ b_ih,
    const float* __restrict__ W_hh, const float* __restrict__ b_hh,
    const float* __restrict__ W1,   const float* __restrict__ b1,
    const float* __restrict__ W2,   const float* __restrict__ b2,
    const float* __restrict__ W3,   const float* __restrict__ b3,
    float* __restrict__ out)
{
    extern __shared__ float xs[];  // [2][CHUNK][EPB][XS_STRIDE]
    __shared__ float sW1[144], sW2[144], sb1[12], sb2[12], sW3[12], sb3[1];

    const int tid  = threadIdx.x;
    const int e    = tid >> 2;        // quad slot (0..7): elements e (A) and e+8 (B)
    const int sub  = tid & 3;         // 3 h-rows per thread
    const int lane = tid & 31;
    const int bA   = blockIdx.x * EPB + e;       // element A
    const int bB   = bA + 8;                     // element B
    const int j0   = sub * 3;

    for (int i = tid; i < 144; i += NTHREADS) { sW1[i] = W1[i]; sW2[i] = W2[i]; }
    if (tid < 12) { sb1[tid] = b1[tid]; sb2[tid] = b2[tid]; sW3[tid] = W3[tid]; }
    if (tid == 0) sb3[0] = b3[0];

    // Shared weights for both elements (rows j0..j0+2), packed along contraction.
    u64 wih2[3][F_IN / 2], whh2[3][H_DIM / 2], biasp[3];
    #pragma unroll
    for (int c = 0; c < 3; c++) {
        const int j = j0 + c;
        #pragma unroll
        for (int p = 0; p < F_IN / 2; p++)
            wih2[c][p] = pack2(W_ih[j * F_IN + 2 * p], W_ih[j * F_IN + 2 * p + 1]);
        #pragma unroll
        for (int p = 0; p < H_DIM / 2; p++)
            whh2[c][p] = pack2(W_hh[j * H_DIM + 2 * p], W_hh[j * H_DIM + 2 * p + 1]);
        biasp[c] = pack2(b_ih[j] + b_hh[j], 0.0f);
    }

    // cp.async staging: thread (e,sub) loads timesteps {2sub, 2sub+1} for BOTH
    // of its elements: 24 x 16B per chunk.
    const float* srcA = x + ((long)bA * T_LEN + 2 * sub) * F_IN;
    const float* srcB = x + ((long)bB * T_LEN + 2 * sub) * F_IN;
    const unsigned xsb  = smem_u32(xs);
    const unsigned dstA = xsb + (unsigned)(((2 * sub * EPB + e) * XS_STRIDE) * 4);
    const unsigned dstB = dstA + (unsigned)(8 * XS_STRIDE * 4);

    auto load_chunk = [&](int bufidx, int c) {
        const long off = (long)c * (CHUNK * F_IN);
        const unsigned boff = (unsigned)bufidx * (XS_BUF_FLOATS * 4);
        #pragma unroll
        for (int j = 0; j < 12; j++) {
            const int tt_l = j / 6;           // 0 or 1
            const int q    = j % 6;           // 0..5
            const unsigned so = (unsigned)((tt_l * EPB * XS_STRIDE + q * 4) * 4);
            cp_async16(dstA + boff + so, srcA + off + tt_l * F_IN + q * 4);
            cp_async16(dstB + boff + so, srcB + off + tt_l * F_IN + q * 4);
        }
        cp_commit();
    };

    u64 hpA[H_DIM / 2], hpB[H_DIM / 2];
    #pragma unroll
    for (int k = 0; k < H_DIM / 2; k++) { hpA[k] = 0ull; hpB[k] = 0ull; }

    const u64 ZERO2 = 0ull;
    const int qbase = lane & ~3;

    load_chunk(0, 0);

    for (int c = 0; c < NCHUNK; c++) {
        __syncwarp();   // (A) all lanes done reading the buffer we overwrite
        if (c + 1 < NCHUNK) { load_chunk((c + 1) & 1, c + 1); cp_wait<1>(); }
        else                { cp_wait<0>(); }
        __syncwarp();   // (B) chunk c visible to all lanes

        const float* buf = xs + (c & 1) * XS_BUF_FLOATS;

        #pragma unroll
        for (int tt = 0; tt < CHUNK; tt++) {
            const ulonglong2* xrA = (const ulonglong2*)(buf + (tt * EPB + e) * XS_STRIDE);
            const ulonglong2* xrB = (const ulonglong2*)(buf + (tt * EPB + e + 8) * XS_STRIDE);

            // --- input projection, two independent chains interleaved ---
            u64 aA0 = biasp[0], aA1 = biasp[1], aA2 = biasp[2];
            u64 aB0 = biasp[0], aB1 = biasp[1], aB2 = biasp[2];
            #pragma unroll
            for (int q = 0; q < 6; q++) {
                ulonglong2 vA = xrA[q];
                ulonglong2 vB = xrB[q];
                aA0 = fma2(wih2[0][2 * q + 0], vA.x, aA0);
                aB0 = fma2(wih2[0][2 * q + 0], vB.x, aB0);
                aA1 = fma2(wih2[1][2 * q + 0], vA.x, aA1);
                aB1 = fma2(wih2[1][2 * q + 0], vB.x, aB1);
                aA2 = fma2(wih2[2][2 * q + 0], vA.x, aA2);
                aB2 = fma2(wih2[2][2 * q + 0], vB.x, aB2);
                aA0 = fma2(wih2[0][2 * q + 1], vA.y, aA0);
                aB0 = fma2(wih2[0][2 * q + 1], vB.y, aB0);
                aA1 = fma2(wih2[1][2 * q + 1], vA.y, aA1);
                aB1 = fma2(wih2[1][2 * q + 1], vB.y, aB1);
                aA2 = fma2(wih2[2][2 * q + 1], vA.y, aA2);
                aB2 = fma2(wih2[2][2 * q + 1], vB.y, aB2);
            }

            // --- recurrence, split accumulators, both elements interleaved ---
            u64 tA0 = fma2(whh2[0][3], hpA[3], ZERO2);
            u64 tB0 = fma2(whh2[0][3], hpB[3], ZERO2);
            u64 tA1 = fma2(whh2[1][3], hpA[3], ZERO2);
            u64 tB1 = fma2(whh2[1][3], hpB[3], ZERO2);
            u64 tA2 = fma2(whh2[2][3], hpA[3], ZERO2);
            u64 tB2 = fma2(whh2[2][3], hpB[3], ZERO2);
            aA0 = fma2(whh2[0][0], hpA[0], aA0);
            aB0 = fma2(whh2[0][0], hpB[0], aB0);
            aA1 = fma2(whh2[1][0], hpA[0], aA1);
            aB1 = fma2(whh2[1][0], hpB[0], aB1);
            aA2 = fma2(whh2[2][0], hpA[0], aA2);
            aB2 = fma2(whh2[2][0], hpB[0], aB2);
            tA0 = fma2(whh2[0][4], hpA[4], tA0);
            tB0 = fma2(whh2[0][4], hpB[4], tB0);
            tA1 = fma2(whh2[1][4], hpA[4], tA1);
            tB1 = fma2(whh2[1][4], hpB[4], tB1);
            tA2 = fma2(whh2[2][4], hpA[4], tA2);
            tB2 = fma2(whh2[2][4], hpB[4], tB2);
            aA0 = fma2(whh2[0][1], hpA[1], aA0);
            aB0 = fma2(whh2[0][1], hpB[1], aB0);
            aA1 = fma2(whh2[1][1], hpA[1], aA1);
            aB1 = fma2(whh2[1][1], hpB[1], aB1);
            aA2 = fma2(whh2[2][1], hpA[1], aA2);
            aB2 = fma2(whh2[2][1], hpB[1], aB2);
            tA0 = fma2(whh2[0][5], hpA[5], tA0);
            tB0 = fma2(whh2[0][5], hpB[5], tB0);
            tA1 = fma2(whh2[1][5], hpA[5], tA1);
            tB1 = fma2(whh2[1][5], hpB[5], tB1);
            tA2 = fma2(whh2[2][5], hpA[5], tA2);
            tB2 = fma2(whh2[2][5], hpB[5], tB2);
            aA0 = fma2(whh2[0][2], hpA[2], aA0);
            aB0 = fma2(whh2[0][2], hpB[2], aB0);
            aA1 = fma2(whh2[1][2], hpA[2], aA1);
            aB1 = fma2(whh2[1][2], hpB[2], aB1);
            aA2 = fma2(whh2[2][2], hpA[2], aA2);
            aB2 = fma2(whh2[2][2], hpB[2], aB2);

            float hlA0 = tanh_fast(hadd2(add2(aA0, tA0)));
            float hlB0 = tanh_fast(hadd2(add2(aB0, tB0)));
            float hlA1 = tanh_fast(hadd2(add2(aA1, tA1)));
            float hlB1 = tanh_fast(hadd2(add2(aB1, tB1)));
            float hlA2 = tanh_fast(hadd2(add2(aA2, tA2)));
            float hlB2 = tanh_fast(hadd2(add2(aB2, tB2)));

            // --- quad exchange for both elements (independent shfl chains) ---
            float hsA[H_DIM], hsB[H_DIM];
            #pragma unroll
            for (int s = 0; s < 4; s++) {
                hsA[s * 3 + 0] = __shfl_sync(0xffffffffu, hlA0, qbase + s);
                hsB[s * 3 + 0] = __shfl_sync(0xffffffffu, hlB0, qbase + s);
                hsA[s * 3 + 1] = __shfl_sync(0xffffffffu, hlA1, qbase + s);
                hsB[s * 3 + 1] = __shfl_sync(0xffffffffu, hlB1, qbase + s);
                hsA[s * 3 + 2] = __shfl_sync(0xffffffffu, hlA2, qbase + s);
                hsB[s * 3 + 2] = __shfl_sync(0xffffffffu, hlB2, qbase + s);
            }
            #pragma unroll
            for (int p = 0; p < H_DIM / 2; p++) {
                hpA[p] = pack2(hsA[2 * p], hsA[2 * p + 1]);
                hpB[p] = pack2(hsB[2 * p], hsB[2 * p + 1]);
            }
        }
    }

    // MLP head: thread sub==0 of each quad handles both of its elements
    if (sub == 0) {
        #pragma unroll
        for (int el = 0; el < 2; el++) {
            const u64* hp = (el == 0) ? hpA : hpB;
            float h_all[H_DIM];
            #pragma unroll
            for (int p = 0; p < H_DIM / 2; p++) unpack2(hp[p], h_all[2 * p], h_all[2 * p + 1]);
            float o1[H_DIM], o2[H_DIM];
            #pragma unroll
            for (int j = 0; j < H_DIM; j++) {
                float s = sb1[j];
                #pragma unroll
                for (int k = 0; k < H_DIM; k++) s = fmaf(sW1[j * H_DIM + k], h_all[k], s);
                o1[j] = fmaxf(s, 0.0f);
            }
            #pragma unroll
            for (int j = 0; j < H_DIM; j++) {
                float s = sb2[j];
                #pragma unroll
                for (int k = 0; k < H_DIM; k++) s = fmaf(sW2[j * H_DIM + k], o1[k], s);
                o2[j] = fmaxf(s, 0.0f);
            }
            float s = sb3[0];
            #pragma unroll
            for (int k = 0; k < H_DIM; k++) s = fmaf(sW3[k], o2[k], s);
            out[(el == 0) ? bA : bB] = s;
        }
    }
}

extern "C" void kernel_launch(void* const* d_in, const int* in_sizes, int n_in,
                              void* d_out, int out_size) {
    (void)in_sizes; (void)n_in; (void)out_size;
    const float* x    = (const float*)d_in[0];
    const float* W_ih = (const float*)d_in[1];
    const float* b_ih = (const float*)d_in[2];
    const float* W_hh = (const float*)d_in[3];
    const float* b_hh = (const float*)d_in[4];
    const float* W1   = (const float*)d_in[5];
    const float* b1   = (const float*)d_in[6];
    const float* W2   = (const float*)d_in[7];
    const float* b2   = (const float*)d_in[8];
    const float* W3   = (const float*)d_in[9];
    const float* b3   = (const float*)d_in[10];
    float* out = (float*)d_out;

    cudaFuncSetAttribute(rnn_fused_kernel,
                         cudaFuncAttributeMaxDynamicSharedMemorySize, SMEM_BYTES);

    dim3 grid(B_TOT / EPB);   // 512 single-warp blocks
    dim3 block(NTHREADS);     // 32 threads
    rnn_fused_kernel<<<grid, block, SMEM_BYTES>>>(
        x, W_ih, b_ih, W_hh, b_hh, W1, b1, W2, b2, W3, b3, out);
}

// round 11
// speedup vs baseline: 1.1436x; 1.1436x over previous
#include <cuda_runtime.h>

#define B_TOT    8192
#define T_LEN    512
#define F_IN     24
#define H_DIM    12
#define CHUNK    8
#define EPB      8            // batch elements per block (one warp)
#define NTHREADS 32
#define NCHUNK   (T_LEN / CHUNK)
#define XS_STRIDE 28          // padded floats per (tt, elem) row; conflict-free, 16B-aligned
#define XS_BUF_FLOATS (CHUNK * EPB * XS_STRIDE)   // 1792
#define SMEM_BYTES (2 * XS_BUF_FLOATS * 4)        // 14336

typedef unsigned long long u64;

__device__ __forceinline__ unsigned smem_u32(const void* p) {
    return (unsigned)__cvta_generic_to_shared(p);
}
__device__ __forceinline__ void cp_async16(unsigned dst, const void* src) {
    asm volatile("cp.async.cg.shared.global [%0], [%1], 16;\n" :: "r"(dst), "l"(src));
}
__device__ __forceinline__ void cp_commit() {
    asm volatile("cp.async.commit_group;\n" ::: "memory");
}
template <int N> __device__ __forceinline__ void cp_wait() {
    asm volatile("cp.async.wait_group %0;\n" :: "n"(N) : "memory");
}

// ---- packed f32x2 helpers ----
__device__ __forceinline__ u64 pack2(float lo, float hi) {
    u64 d; asm("mov.b64 %0, {%1, %2};" : "=l"(d) : "f"(lo), "f"(hi)); return d;
}
__device__ __forceinline__ void unpack2(u64 d, float& lo, float& hi) {
    asm("mov.b64 {%0, %1}, %2;" : "=f"(lo), "=f"(hi) : "l"(d));
}
__device__ __forceinline__ u64 fma2(u64 a, u64 b, u64 c) {
    u64 d; asm("fma.rn.f32x2 %0, %1, %2, %3;" : "=l"(d) : "l"(a), "l"(b), "l"(c)); return d;
}
__device__ __forceinline__ u64 add2(u64 a, u64 b) {
    u64 d; asm("add.rn.f32x2 %0, %1, %2;" : "=l"(d) : "l"(a), "l"(b)); return d;
}
__device__ __forceinline__ float hadd2(u64 a) {
    float lo, hi; unpack2(a, lo, hi); return lo + hi;
}

// tanh on PRESCALED input: sx = 2*log2(e)*x  ->  tanh(x) = 1 - 2*rcp(2^sx + 1).
// Saturates correctly at +/-inf; |err| ~1e-7.
__device__ __forceinline__ float tanh_prescaled(float sx) {
    float e;
    asm("ex2.approx.f32 %0, %1;" : "=f"(e) : "f"(sx));
    float r;
    asm("rcp.approx.f32 %0, %1;" : "=f"(r) : "f"(e + 1.0f));
    return fmaf(-2.0f, r, 1.0f);
}

#define SCALE_T 2.885390082f   // 2*log2(e)

__global__ void __launch_bounds__(NTHREADS) rnn_fused_kernel(
    const float* __restrict__ x,
    const float* __restrict__ W_ih, const float* __restrict__ b_ih,
    const float* __restrict__ W_hh, const float* __restrict__ b_hh,
    const float* __restrict__ W1,   const float* __restrict__ b1,
    const float* __restrict__ W2,   const float* __restrict__ b2,
    const float* __restrict__ W3,   const float* __restrict__ b3,
    float* __restrict__ out)
{
    extern __shared__ float xs[];  // [2][CHUNK][EPB][XS_STRIDE]
    __shared__ float sW1[144], sW2[144], sb1[12], sb2[12], sW3[12], sb3[1];

    const int tid  = threadIdx.x;
    const int e    = tid >> 2;        // element within block (0..7)
    const int sub  = tid & 3;         // 3 h-rows per thread
    const int b    = blockIdx.x * EPB + e;
    const int j0   = sub * 3;

    for (int i = tid; i < 144; i += NTHREADS) { sW1[i] = W1[i]; sW2[i] = W2[i]; }
    if (tid < 12) { sb1[tid] = b1[tid]; sb2[tid] = b2[tid]; sW3[tid] = W3[tid]; }
    if (tid == 0) sb3[0] = b3[0];

    // Per-thread weights, PRESCALED by 2*log2(e) and packed along contraction.
    u64 wih2[3][F_IN / 2], whh2[3][H_DIM / 2], biasp[3];
    #pragma unroll
    for (int c = 0; c < 3; c++) {
        const int j = j0 + c;
        #pragma unroll
        for (int p = 0; p < F_IN / 2; p++)
            wih2[c][p] = pack2(SCALE_T * W_ih[j * F_IN + 2 * p],
                               SCALE_T * W_ih[j * F_IN + 2 * p + 1]);
        #pragma unroll
        for (int p = 0; p < H_DIM / 2; p++)
            whh2[c][p] = pack2(SCALE_T * W_hh[j * H_DIM + 2 * p],
                               SCALE_T * W_hh[j * H_DIM + 2 * p + 1]);
        biasp[c] = pack2(SCALE_T * (b_ih[j] + b_hh[j]), 0.0f);
    }

    // cp.async staging: thread (e,sub) loads timesteps {sub, sub+4} of elem e.
    const float* src0 = x + ((long)b * T_LEN + sub) * F_IN;
    const unsigned xsb  = smem_u32(xs);
    const unsigned dstL = xsb + (unsigned)(((sub * EPB + e) * XS_STRIDE) * 4);
    const unsigned dstH = xsb + (unsigned)((((sub + 4) * EPB + e) * XS_STRIDE) * 4);

    auto load_chunk = [&](int bufidx, int c) {
        const float* s = src0 + (long)c * (CHUNK * F_IN);
        const unsigned boff = (unsigned)bufidx * (XS_BUF_FLOATS * 4);
        #pragma unroll
        for (int q = 0; q < 6; q++) {
            cp_async16(dstL + boff + (unsigned)(q * 16), s + q * 4);
            cp_async16(dstH + boff + (unsigned)(q * 16), s + 4 * F_IN + q * 4);
        }
        cp_commit();
    };

    u64 hp[H_DIM / 2];
    #pragma unroll
    for (int k = 0; k < H_DIM / 2; k++) hp[k] = 0ull;

    const u64 ZERO2 = 0ull;
    const int qbase = tid & ~3;

    load_chunk(0, 0);

    for (int c = 0; c < NCHUNK; c++) {
        cp_wait<0>();   // own group for chunk c complete
        __syncwarp();   // everyone's chunk-c writes visible; all past chunk c-1
        if (c + 1 < NCHUNK) load_chunk((c + 1) & 1, c + 1);   // overlaps consume

        const float* buf = xs + (c & 1) * XS_BUF_FLOATS;

        #pragma unroll
        for (int tt = 0; tt < CHUNK; tt++) {
            // x row: 6 conflict-free LDS.128 -> 12 packed pairs
            const ulonglong2* xr = (const ulonglong2*)(buf + (tt * EPB + e) * XS_STRIDE);
            u64 a0 = biasp[0], a1 = biasp[1], a2 = biasp[2];
            #pragma unroll
            for (int q = 0; q < 6; q++) {
                ulonglong2 v = xr[q];
                a0 = fma2(wih2[0][2 * q + 0], v.x, a0);
                a1 = fma2(wih2[1][2 * q + 0], v.x, a1);
                a2 = fma2(wih2[2][2 * q + 0], v.x, a2);
                a0 = fma2(wih2[0][2 * q + 1], v.y, a0);
                a1 = fma2(wih2[1][2 * q + 1], v.y, a1);
                a2 = fma2(wih2[2][2 * q + 1], v.y, a2);
            }
            // recurrence: split accumulators (3-deep chains)
            u64 t0 = fma2(whh2[0][3], hp[3], ZERO2);
            u64 t1 = fma2(whh2[1][3], hp[3], ZERO2);
            u64 t2 = fma2(whh2[2][3], hp[3], ZERO2);
            a0 = fma2(whh2[0][0], hp[0], a0);
            a1 = fma2(whh2[1][0], hp[0], a1);
            a2 = fma2(whh2[2][0], hp[0], a2);
            t0 = fma2(whh2[0][4], hp[4], t0);
            t1 = fma2(whh2[1][4], hp[4], t1);
            t2 = fma2(whh2[2][4], hp[4], t2);
            a0 = fma2(whh2[0][1], hp[1], a0);
            a1 = fma2(whh2[1][1], hp[1], a1);
            a2 = fma2(whh2[2][1], hp[1], a2);
            t0 = fma2(whh2[0][5], hp[5], t0);
            t1 = fma2(whh2[1][5], hp[5], t1);
            t2 = fma2(whh2[2][5], hp[5], t2);
            a0 = fma2(whh2[0][2], hp[2], a0);
            a1 = fma2(whh2[1][2], hp[2], a1);
            a2 = fma2(whh2[2][2], hp[2], a2);

            float hl0 = tanh_prescaled(hadd2(add2(a0, t0)));
            float hl1 = tanh_prescaled(hadd2(add2(a1, t1)));
            float hl2 = tanh_prescaled(hadd2(add2(a2, t2)));

            // quad exchange: 12 shfl, repack into 6 pairs
            float hs[H_DIM];
            #pragma unroll
            for (int s = 0; s < 4; s++) {
                hs[s * 3 + 0] = __shfl_sync(0xffffffffu, hl0, qbase + s);
                hs[s * 3 + 1] = __shfl_sync(0xffffffffu, hl1, qbase + s);
                hs[s * 3 + 2] = __shfl_sync(0xffffffffu, hl2, qbase + s);
            }
            #pragma unroll
            for (int p = 0; p < H_DIM / 2; p++)
                hp[p] = pack2(hs[2 * p], hs[2 * p + 1]);
        }
    }

    __syncwarp();
    // MLP head: one thread per element
    if (sub == 0) {
        float h_all[H_DIM];
        #pragma unroll
        for (int p = 0; p < H_DIM / 2; p++) unpack2(hp[p], h_all[2 * p], h_all[2 * p + 1]);
        float o1[H_DIM], o2[H_DIM];
        #pragma unroll
        for (int j = 0; j < H_DIM; j++) {
            float s = sb1[j];
            #pragma unroll
            for (int k = 0; k < H_DIM; k++) s = fmaf(sW1[j * H_DIM + k], h_all[k], s);
            o1[j] = fmaxf(s, 0.0f);
        }
        #pragma unroll
        for (int j = 0; j < H_DIM; j++) {
            float s = sb2[j];
            #pragma unroll
            for (int k = 0; k < H_DIM; k++) s = fmaf(sW2[j * H_DIM + k], o1[k], s);
            o2[j] = fmaxf(s, 0.0f);
        }
        float s = sb3[0];
        #pragma unroll
        for (int k = 0; k < H_DIM; k++) s = fmaf(sW3[k], o2[k], s);
        out[b] = s;
    }
}

extern "C" void kernel_launch(void* const* d_in, const int* in_sizes, int n_in,
                              void* d_out, int out_size) {
    (void)in_sizes; (void)n_in; (void)out_size;
    const float* x    = (const float*)d_in[0];
    const float* W_ih = (const float*)d_in[1];
    const float* b_ih = (const float*)d_in[2];
    const float* W_hh = (const float*)d_in[3];
    const float* b_hh = (const float*)d_in[4];
    const float* W1   = (const float*)d_in[5];
    const float* b1   = (const float*)d_in[6];
    const float* W2   = (const float*)d_in[7];
    const float* b2   = (const float*)d_in[8];
    const float* W3   = (const float*)d_in[9];
    const float* b3   = (const float*)d_in[10];
    float* out = (float*)d_out;

    cudaFuncSetAttribute(rnn_fused_kernel,
                         cudaFuncAttributeMaxDynamicSharedMemorySize, SMEM_BYTES);

    dim3 grid(B_TOT / EPB);   // 1024 single-warp blocks
    dim3 block(NTHREADS);
    rnn_fused_kernel<<<grid, block, SMEM_BYTES>>>(
        x, W_ih, b_ih, W_hh, b_hh, W1, b1, W2, b2, W3, b3, out);
}